// round 6
// baseline (speedup 1.0000x reference)
#include <cuda_runtime.h>
#include <cstdint>

// Problem constants
#define BATCH 16
#define NA    3
#define NC    20
#define NATTR 25          // 5 + NC
#define IH    52
#define IW    52
#define HW    2704        // IH*IW
#define NBOX  8112        // NA*HW
#define NPAD  8192
#define TOPK  2048
#define NWORDS (TOPK / 64)    // 32 u64 words per suppression row
#define NBLK   (TOPK / 64)    // 32 blocks of 64 candidates
#define STRIDE_F 8.0f

typedef unsigned long long u64;

// Accurate libdevice expf (XLA's f32 exp lowering), immune to --use_fast_math.
extern "C" __device__ float __nv_expf(float);

// Scratch (allocation-free: __device__ globals)
__device__ float g_conf[BATCH][NBOX];
__device__ int   g_cls [BATCH][NBOX];
__device__ int   g_top [BATCH][TOPK];

// NMS staging
__device__ float g_x1[BATCH][TOPK];
__device__ float g_y1[BATCH][TOPK];
__device__ float g_x2[BATCH][TOPK];
__device__ float g_y2[BATCH][TOPK];
__device__ float g_ar[BATCH][TOPK];
__device__ short g_cl[BATCH][TOPK];
__device__ u64   g_vab[BATCH][NWORDS];          // validity bitmask
__device__ u64   g_mask[BATCH][TOPK][NWORDS];   // 8 MB suppression matrix

// ---------------------------------------------------------------------------
// Bitwise replica of XLA:GPU's tanh (llvm_ir::EmitFastTanh).
// ---------------------------------------------------------------------------
__device__ __forceinline__ float xla_tanhf(float x) {
    float ax = fabsf(x);
    float xc = fminf(fmaxf(x, -7.90531110763549805f), 7.90531110763549805f);
    float x2 = __fmul_rn(xc, xc);
    float p = -2.76076847742355e-16f;
    p = __fmaf_rn(x2, p, 2.00018790482477e-13f);
    p = __fmaf_rn(x2, p, -8.60467152213735e-11f);
    p = __fmaf_rn(x2, p, 5.12229709037114e-08f);
    p = __fmaf_rn(x2, p, 1.48572235717979e-05f);
    p = __fmaf_rn(x2, p, 6.37261928875436e-04f);
    p = __fmaf_rn(x2, p, 4.89352455891786e-03f);
    p = __fmul_rn(xc, p);
    float q = 1.19825839466702e-06f;
    q = __fmaf_rn(x2, q, 1.18534705686654e-04f);
    q = __fmaf_rn(x2, q, 2.26843463243900e-03f);
    q = __fmaf_rn(x2, q, 4.89352518554385e-03f);
    float r = __fdiv_rn(p, q);
    return (ax < 0.0004f) ? x : r;
}

__device__ __forceinline__ float sigmoid_xla(float x) {
    float t = xla_tanhf(__fmul_rn(0.5f, x));
    return __fmaf_rn(0.5f, t, 0.5f);
}

// ---------------------------------------------------------------------------
// Kernel 1: decode (unchanged — measured 20us).
// ---------------------------------------------------------------------------
__global__ void decode_kernel(const float* __restrict__ in,
                              const float* __restrict__ anchors,
                              float* __restrict__ out) {
    __shared__ float s_out[128 * NATTR];

    int t = blockIdx.x * 128 + threadIdx.x;     // grid sized exactly: no tail
    int b = t / NBOX, n = t % NBOX;
    int a = n / HW,   r = n % HW;
    int gy = r / IW,  gx = r % IW;

    const float* base = in + ((size_t)(b * NA + a) * NATTR) * HW + r;
    float t0 = base[0 * HW];
    float t1 = base[1 * HW];
    float t2 = base[2 * HW];
    float t3 = base[3 * HW];
    float t4 = base[4 * HW];

    float aw = __fdiv_rn(anchors[a * 2 + 0], STRIDE_F);
    float ah = __fdiv_rn(anchors[a * 2 + 1], STRIDE_F);

    float sx = sigmoid_xla(t0);
    float sy = sigmoid_xla(t1);
    float bx = __fmul_rn(__fadd_rn(sx, (float)gx), STRIDE_F);
    float by = __fmul_rn(__fadd_rn(sy, (float)gy), STRIDE_F);
    float bw = __fmul_rn(__fmul_rn(__nv_expf(t2), aw), STRIDE_F);
    float bh = __fmul_rn(__fmul_rn(__nv_expf(t3), ah), STRIDE_F);
    float conf = sigmoid_xla(t4);

    float* so = s_out + threadIdx.x * NATTR;
    so[0] = bx; so[1] = by; so[2] = bw; so[3] = bh; so[4] = conf;

    float bestv = -3.402823466e+38f;
    int best = 0;
#pragma unroll
    for (int c = 0; c < NC; c++) {
        float v = sigmoid_xla(base[(5 + c) * HW]);
        so[5 + c] = v;
        if (v > bestv) { bestv = v; best = c; }
    }
    g_conf[b][n] = conf;
    g_cls[b][n]  = best;
    __syncthreads();

    float* oblk = out + (size_t)(blockIdx.x) * 128 * NATTR;
    for (int k = threadIdx.x; k < 128 * NATTR; k += 128)
        oblk[k] = s_out[k];
}

// ---------------------------------------------------------------------------
// Kernel 2: per-batch bitonic sort, register-resident (cyclic layout), with
// the NMS prep fused into the epilogue (corners/area/class/valid-bitmask).
// ---------------------------------------------------------------------------
extern __shared__ u64 s_keys[];

__device__ __forceinline__ u64 cex(u64 a, u64 v, bool lower, bool desc) {
    u64 mx = a > v ? a : v;
    u64 mn = a > v ? v : a;
    return desc ? (lower ? mx : mn) : (lower ? mn : mx);
}

__global__ void sort_kernel(const float* __restrict__ out,
                            float* __restrict__ out_topidx) {
    int b = blockIdx.x;
    int t = threadIdx.x;                        // 1024 threads

    if (t < NWORDS) g_vab[b][t] = 0ull;         // zero validity bitmask

    u64 r[8];
#pragma unroll
    for (int m = 0; m < 8; m++) {
        int i = m * 1024 + t;
        u64 kk = 0ull;
        if (i < NBOX) {
            unsigned cb = __float_as_uint(g_conf[b][i]);
            kk = ((u64)cb << 32) | (unsigned)(0xFFFFFFFFu - (unsigned)i);
        }
        r[m] = kk;
    }

    for (int k2 = 2; k2 <= NPAD; k2 <<= 1) {
        for (int j = k2 >> 1; j > 0; j >>= 1) {
            if (j >= 1024) {
                int s = j >> 10;                // slot stride 1,2,4
#pragma unroll
                for (int m = 0; m < 8; m++) {
                    if (!(m & s)) {
                        int lo = m, hi = m | s;
                        bool desc = (((lo * 1024 + t) & k2) == 0);
                        u64 a = r[lo], v = r[hi];
                        bool sw = desc ? (a < v) : (a > v);
                        if (sw) { r[lo] = v; r[hi] = a; }
                    }
                }
            } else if (j >= 32) {
#pragma unroll
                for (int m = 0; m < 8; m++) s_keys[m * 1024 + t] = r[m];
                __syncthreads();
#pragma unroll
                for (int m = 0; m < 8; m++) {
                    int i = m * 1024 + t;
                    u64 v = s_keys[i ^ j];
                    bool lower = ((i & j) == 0);
                    bool desc  = ((i & k2) == 0);
                    r[m] = cex(r[m], v, lower, desc);
                }
                __syncthreads();
            } else {
#pragma unroll
                for (int m = 0; m < 8; m++) {
                    int i = m * 1024 + t;
                    u64 v = __shfl_xor_sync(0xFFFFFFFFu, r[m], j);
                    bool lower = ((t & j) == 0);
                    bool desc  = ((i & k2) == 0);
                    r[m] = cex(r[m], v, lower, desc);
                }
            }
        }
    }

    // Epilogue: elements i < TOPK live in slots m = 0,1.  Emit top_idx and
    // fused NMS prep (conf comes free from the key's high 32 bits).
#pragma unroll
    for (int m = 0; m < 2; m++) {
        int i = m * 1024 + t;
        u64 kk = r[m];
        int n = (int)(0xFFFFFFFFu - (unsigned)(kk & 0xFFFFFFFFull));
        g_top[b][i] = n;
        out_topidx[b * TOPK + i] = (float)n;

        const float* o = out + ((size_t)b * NBOX + n) * NATTR;
        float cx = o[0], cy = o[1], w = o[2], h = o[3];
        float conf = __uint_as_float((unsigned)(kk >> 32));
        float hw2 = __fmul_rn(w, 0.5f);
        float hh2 = __fmul_rn(h, 0.5f);
        float x1 = __fsub_rn(cx, hw2);
        float y1 = __fsub_rn(cy, hh2);
        float x2 = __fadd_rn(cx, hw2);
        float y2 = __fadd_rn(cy, hh2);
        g_x1[b][i] = x1; g_y1[b][i] = y1; g_x2[b][i] = x2; g_y2[b][i] = y2;
        g_ar[b][i] = __fmul_rn(__fadd_rn(__fsub_rn(x2, x1), 1.0f),
                               __fadd_rn(__fsub_rn(y2, y1), 1.0f));
        g_cl[b][i] = (short)g_cls[b][n];
        if (conf >= 0.5f)
            atomicOr(&g_vab[b][i >> 6], 1ull << (i & 63));
    }
}

// ---------------------------------------------------------------------------
// Kernel 3: suppression mask (unchanged — measured 19.8us).
// ---------------------------------------------------------------------------
__global__ void nms_mask(void) {
    int jb = blockIdx.x, ib = blockIdx.y, b = blockIdx.z;
    if (jb < ib) return;

    __shared__ float jx1[64], jy1[64], jx2[64], jy2[64], jar[64];
    __shared__ u64 s_cm[NC];

    int t = threadIdx.x;
    int j0 = jb * 64;
    if (t < NC) s_cm[t] = 0ull;
    __syncthreads();
    jx1[t] = g_x1[b][j0 + t];
    jy1[t] = g_y1[b][j0 + t];
    jx2[t] = g_x2[b][j0 + t];
    jy2[t] = g_y2[b][j0 + t];
    jar[t] = g_ar[b][j0 + t];
    atomicOr(&s_cm[g_cl[b][j0 + t]], 1ull << t);
    __syncthreads();

    int i = ib * 64 + t;
    float xi1 = g_x1[b][i], yi1 = g_y1[b][i];
    float xi2 = g_x2[b][i], yi2 = g_y2[b][i];
    float ai  = g_ar[b][i];
    short ci  = g_cl[b][i];

    u64 mm = s_cm[ci];
    if (jb == ib) mm = (t < 63) ? (mm & (~0ull << (t + 1))) : 0ull;

    u64 bits = 0ull;
    while (mm) {
        int jj = __ffsll((long long)mm) - 1;
        mm &= mm - 1;
        float ix1 = fmaxf(xi1, jx1[jj]);
        float iy1 = fmaxf(yi1, jy1[jj]);
        float ix2 = fminf(xi2, jx2[jj]);
        float iy2 = fminf(yi2, jy2[jj]);
        float iw = __fadd_rn(__fsub_rn(ix2, ix1), 1.0f); iw = fmaxf(iw, 0.0f);
        float ih = __fadd_rn(__fsub_rn(iy2, iy1), 1.0f); ih = fmaxf(ih, 0.0f);
        float inter = __fmul_rn(iw, ih);
        float den = __fadd_rn(__fsub_rn(__fadd_rn(ai, jar[jj]), inter), 1e-16f);
        float iou = __fdiv_rn(inter, den);
        if (iou >= 0.4f) bits |= 1ull << jj;
    }
    g_mask[b][i][jb] = bits;
}

// ---------------------------------------------------------------------------
// Kernel 4: block-greedy reduce — one warp per batch, 64 candidates/step.
// Owner lane resolves a whole 64-candidate word locally via ffs over the
// diagonal block; one 64-bit shfl broadcasts the keep mask; all lanes apply
// kept rows to their own removed-word in parallel. Rows double-buffered into
// SMEM with cp.async.
// ---------------------------------------------------------------------------
__device__ __forceinline__ void cp16(void* saddr, const void* gaddr) {
    unsigned s = (unsigned)__cvta_generic_to_shared(saddr);
    asm volatile("cp.async.cg.shared.global [%0], [%1], 16;" :: "r"(s), "l"(gaddr));
}

__global__ void nms_reduce(float* __restrict__ keep_out) {
    __shared__ __align__(16) u64 sbuf[2][64][NWORDS];   // 32 KB

    int b = blockIdx.x;
    int lane = threadIdx.x;                     // 32 threads

    u64 vaw = g_vab[b][lane];                   // validity bits of word `lane`
    u64 removed = 0ull;

    // stage(blk, buf): 64 rows x 32 u64 = 16 KB, 32 x 16B chunks per lane
#define STAGE(blk, buf)                                                     \
    {                                                                       \
        _Pragma("unroll")                                                   \
        for (int k = 0; k < 32; k++) {                                      \
            int chunk = lane + 32 * k;                                      \
            int row = chunk >> 4, off = (chunk & 15) * 2;                   \
            cp16(&sbuf[buf][row][off], &g_mask[b][(blk) * 64 + row][off]);  \
        }                                                                   \
    }

    STAGE(0, 0);
    asm volatile("cp.async.commit_group;");
    STAGE(1, 1);
    asm volatile("cp.async.commit_group;");
    asm volatile("cp.async.wait_group 1;");
    __syncwarp();

    for (int bk = 0; bk < NBLK; bk++) {
        int buf = bk & 1;

        // owner lane (== bk) resolves its 64 candidates locally
        u64 keep64 = 0ull;
        if (lane == bk) {
            u64 cand = vaw & ~removed;
            while (cand) {
                int u = __ffsll((long long)cand) - 1;
                keep64 |= 1ull << u;
                u64 dia = sbuf[buf][u][bk];       // bits only for j > u
                cand &= ~(1ull << u);
                cand &= ~dia;
            }
        }
        keep64 = __shfl_sync(0xFFFFFFFFu, keep64, bk);

        // write keep for this block (2 candidates per lane)
        {
            int i0 = bk * 64;
            keep_out[b * TOPK + i0 + lane] =
                ((keep64 >> lane) & 1ull) ? 1.0f : 0.0f;
            keep_out[b * TOPK + i0 + 32 + lane] =
                ((keep64 >> (lane + 32)) & 1ull) ? 1.0f : 0.0f;
        }

        // all lanes apply kept rows to their own removed word
        if (lane > bk) {
            u64 kk = keep64;
            while (kk) {
                int u = __ffsll((long long)kk) - 1;
                kk &= kk - 1;
                removed |= sbuf[buf][u][lane];
            }
        }
        __syncwarp();

        // stage block bk+2 into the buffer we just finished reading
        if (bk + 2 < NBLK) STAGE(bk + 2, buf);
        asm volatile("cp.async.commit_group;");
        asm volatile("cp.async.wait_group 1;");
        __syncwarp();
    }
#undef STAGE
}

// ---------------------------------------------------------------------------
// Launch: out = [output(B*NBOX*NATTR) | top_idx(B*TOPK) | keep(B*TOPK)] float32
// ---------------------------------------------------------------------------
extern "C" void kernel_launch(void* const* d_in, const int* in_sizes, int n_in,
                              void* d_out, int out_size) {
    (void)in_sizes; (void)n_in; (void)out_size;
    const float* in      = (const float*)d_in[0];
    const float* anchors = (const float*)d_in[1];
    float* out      = (float*)d_out;
    float* top_out  = out + (size_t)BATCH * NBOX * NATTR;
    float* keep_out = top_out + (size_t)BATCH * TOPK;

    int total = BATCH * NBOX;                 // 129792 = 128 * 1014, no tail
    decode_kernel<<<total / 128, 128>>>(in, anchors, out);

    (void)cudaFuncSetAttribute(sort_kernel,
                               cudaFuncAttributeMaxDynamicSharedMemorySize,
                               NPAD * (int)sizeof(u64));
    sort_kernel<<<BATCH, 1024, NPAD * sizeof(u64)>>>(out, top_out);

    nms_mask<<<dim3(TOPK / 64, TOPK / 64, BATCH), 64>>>();
    nms_reduce<<<BATCH, 32>>>(keep_out);
}

// round 7
// speedup vs baseline: 1.7985x; 1.7985x over previous
#include <cuda_runtime.h>
#include <cstdint>

// Problem constants
#define BATCH 16
#define NA    3
#define NC    20
#define NATTR 25          // 5 + NC
#define IH    52
#define IW    52
#define HW    2704        // IH*IW
#define NBOX  8112        // NA*HW
#define NPAD  8192
#define TOPK  2048
#define NWORDS (TOPK / 64)    // 32 u64 words per suppression row
#define NBLK   (TOPK / 64)    // 32 blocks of 64 candidates
#define STRIDE_F 8.0f

typedef unsigned long long u64;

// Accurate libdevice expf (XLA's f32 exp lowering), immune to --use_fast_math.
extern "C" __device__ float __nv_expf(float);

// Scratch (allocation-free: __device__ globals)
__device__ float g_conf[BATCH][NBOX];
__device__ int   g_cls [BATCH][NBOX];
__device__ u64   g_runA[BATCH][NPAD];
__device__ u64   g_runB[BATCH][NPAD];

// NMS staging
__device__ float g_x1[BATCH][TOPK];
__device__ float g_y1[BATCH][TOPK];
__device__ float g_x2[BATCH][TOPK];
__device__ float g_y2[BATCH][TOPK];
__device__ float g_ar[BATCH][TOPK];
__device__ short g_cl[BATCH][TOPK];
__device__ u64   g_vab[BATCH][NWORDS];          // validity bitmask
__device__ u64   g_mask[BATCH][TOPK][NWORDS];   // 8 MB suppression matrix

// ---------------------------------------------------------------------------
// Bitwise replica of XLA:GPU's tanh (llvm_ir::EmitFastTanh).
// ---------------------------------------------------------------------------
__device__ __forceinline__ float xla_tanhf(float x) {
    float ax = fabsf(x);
    float xc = fminf(fmaxf(x, -7.90531110763549805f), 7.90531110763549805f);
    float x2 = __fmul_rn(xc, xc);
    float p = -2.76076847742355e-16f;
    p = __fmaf_rn(x2, p, 2.00018790482477e-13f);
    p = __fmaf_rn(x2, p, -8.60467152213735e-11f);
    p = __fmaf_rn(x2, p, 5.12229709037114e-08f);
    p = __fmaf_rn(x2, p, 1.48572235717979e-05f);
    p = __fmaf_rn(x2, p, 6.37261928875436e-04f);
    p = __fmaf_rn(x2, p, 4.89352455891786e-03f);
    p = __fmul_rn(xc, p);
    float q = 1.19825839466702e-06f;
    q = __fmaf_rn(x2, q, 1.18534705686654e-04f);
    q = __fmaf_rn(x2, q, 2.26843463243900e-03f);
    q = __fmaf_rn(x2, q, 4.89352518554385e-03f);
    float r = __fdiv_rn(p, q);
    return (ax < 0.0004f) ? x : r;
}

__device__ __forceinline__ float sigmoid_xla(float x) {
    float t = xla_tanhf(__fmul_rn(0.5f, x));
    return __fmaf_rn(0.5f, t, 0.5f);
}

// ---------------------------------------------------------------------------
// Kernel 1: decode (identical math; 256-thread blocks).
// ---------------------------------------------------------------------------
__global__ void decode_kernel(const float* __restrict__ in,
                              const float* __restrict__ anchors,
                              float* __restrict__ out) {
    __shared__ float s_out[256 * NATTR];

    int t = blockIdx.x * 256 + threadIdx.x;     // grid sized exactly: no tail
    int b = t / NBOX, n = t % NBOX;
    int a = n / HW,   r = n % HW;
    int gy = r / IW,  gx = r % IW;

    const float* base = in + ((size_t)(b * NA + a) * NATTR) * HW + r;
    float t0 = base[0 * HW];
    float t1 = base[1 * HW];
    float t2 = base[2 * HW];
    float t3 = base[3 * HW];
    float t4 = base[4 * HW];

    float aw = __fdiv_rn(anchors[a * 2 + 0], STRIDE_F);
    float ah = __fdiv_rn(anchors[a * 2 + 1], STRIDE_F);

    float sx = sigmoid_xla(t0);
    float sy = sigmoid_xla(t1);
    float bx = __fmul_rn(__fadd_rn(sx, (float)gx), STRIDE_F);
    float by = __fmul_rn(__fadd_rn(sy, (float)gy), STRIDE_F);
    float bw = __fmul_rn(__fmul_rn(__nv_expf(t2), aw), STRIDE_F);
    float bh = __fmul_rn(__fmul_rn(__nv_expf(t3), ah), STRIDE_F);
    float conf = sigmoid_xla(t4);

    float* so = s_out + threadIdx.x * NATTR;
    so[0] = bx; so[1] = by; so[2] = bw; so[3] = bh; so[4] = conf;

    float bestv = -3.402823466e+38f;
    int best = 0;
#pragma unroll
    for (int c = 0; c < NC; c++) {
        float v = sigmoid_xla(base[(5 + c) * HW]);
        so[5 + c] = v;
        if (v > bestv) { bestv = v; best = c; }
    }
    g_conf[b][n] = conf;
    g_cls[b][n]  = best;
    __syncthreads();

    float* oblk = out + (size_t)blockIdx.x * 256 * NATTR;
    for (int k = threadIdx.x; k < 256 * NATTR; k += 256)
        oblk[k] = s_out[k];
}

// ---------------------------------------------------------------------------
// Top-K pipeline: truncated tournament merge.
// key = (conf_bits << 32) | (0xFFFFFFFF - idx); desc order = conf desc then
// idx asc (matches stable top_k). Run r at any level sorted DESC iff
// popcount(r) even -> every concatenated sibling pair is bitonic.
// ---------------------------------------------------------------------------
__device__ __forceinline__ u64 cex(u64 a, u64 v, bool lower, bool desc) {
    u64 mx = a > v ? a : v;
    u64 mn = a > v ? v : a;
    return desc ? (lower ? mx : mn) : (lower ? mn : mx);
}

// 2a: local sort of 8 x 1024-element runs per batch. grid (8, BATCH), 1024 thr.
__global__ void local_sort(void) {
    __shared__ u64 s[1024];
    int c = blockIdx.x, b = blockIdx.y, t = threadIdx.x;
    int i = c * 1024 + t;
    u64 kk = 0ull;
    if (i < NBOX) {
        unsigned cb = __float_as_uint(g_conf[b][i]);
        kk = ((u64)cb << 32) | (unsigned)(0xFFFFFFFFu - (unsigned)i);
    }
    bool dirDesc = ((__popc(c) & 1) == 0);
    s[t] = kk;
    __syncthreads();
    u64 mine = kk;
    for (int k2 = 2; k2 <= 1024; k2 <<= 1) {
        for (int j = k2 >> 1; j > 0; j >>= 1) {
            u64 part = s[t ^ j];
            bool lower = (t & j) == 0;
            bool descb = (((t & k2) == 0) == dirDesc);
            mine = cex(mine, part, lower, descb);
            __syncthreads();
            s[t] = mine;
            __syncthreads();
        }
    }
    g_runA[b][c * 1024 + t] = mine;
}

// 2b: merge pass. RUNLEN=1024: full merge 1024+1024 -> 2048.
//     RUNLEN=2048: truncating merge 2048+2048 -> top 2048 (bitonic split).
// grid (nMerges, BATCH), 1024 threads, 2 elements per thread.
template<int RUNLEN, int SRCA>
__global__ void merge_pass(void) {
    __shared__ u64 s[2048];
    int m = blockIdx.x, b = blockIdx.y, t = threadIdx.x;
    const u64* in = SRCA ? g_runA[b] : g_runB[b];
    u64* outp     = SRCA ? g_runB[b] : g_runA[b];
    const u64* A  = in + 2 * m * RUNLEN;
    const u64* Bp = A + RUNLEN;
    bool dirDesc = ((__popc(m) & 1) == 0);

    if (RUNLEN == 1024) {
        s[t]        = A[t];
        s[t + 1024] = Bp[t];
    } else {
        u64 a0 = A[t],        b0 = Bp[t];
        u64 a1 = A[t + 1024], b1 = Bp[t + 1024];
        s[t]        = a0 > b0 ? a0 : b0;    // top half of bitonic split
        s[t + 1024] = a1 > b1 ? a1 : b1;
    }
    __syncthreads();
    for (int j = 1024; j > 0; j >>= 1) {
        int lo = ((t & ~(j - 1)) << 1) | (t & (j - 1));
        int hi = lo + j;
        u64 a = s[lo], v = s[hi];
        bool sw = dirDesc ? (a < v) : (a > v);
        if (sw) { s[lo] = v; s[hi] = a; }
        __syncthreads();
    }
    outp[m * 2048 + t]        = s[t];
    outp[m * 2048 + 1024 + t] = s[t + 1024];
}

// 2c: final truncating merge (desc) + fused NMS prep. grid (BATCH), 1024 thr.
__global__ void merge_final(const float* __restrict__ out,
                            float* __restrict__ out_topidx) {
    __shared__ u64 s[2048];
    __shared__ unsigned s_vab32[64];
    int b = blockIdx.x, t = threadIdx.x;
    if (t < 64) s_vab32[t] = 0u;

    const u64* A  = g_runA[b];
    const u64* Bp = A + 2048;
    u64 a0 = A[t],        b0 = Bp[t];
    u64 a1 = A[t + 1024], b1 = Bp[t + 1024];
    s[t]        = a0 > b0 ? a0 : b0;
    s[t + 1024] = a1 > b1 ? a1 : b1;
    __syncthreads();
    for (int j = 1024; j > 0; j >>= 1) {
        int lo = ((t & ~(j - 1)) << 1) | (t & (j - 1));
        int hi = lo + j;
        u64 a = s[lo], v = s[hi];
        if (a < v) { s[lo] = v; s[hi] = a; }   // desc
        __syncthreads();
    }

#pragma unroll
    for (int q = 0; q < 2; q++) {
        int i = t + q * 1024;
        u64 kk = s[i];
        int n = (int)(0xFFFFFFFFu - (unsigned)(kk & 0xFFFFFFFFull));
        out_topidx[b * TOPK + i] = (float)n;

        const float* o = out + ((size_t)b * NBOX + n) * NATTR;
        float cx = o[0], cy = o[1], w = o[2], h = o[3];
        float conf = __uint_as_float((unsigned)(kk >> 32));
        float hw2 = __fmul_rn(w, 0.5f);
        float hh2 = __fmul_rn(h, 0.5f);
        float x1 = __fsub_rn(cx, hw2);
        float y1 = __fsub_rn(cy, hh2);
        float x2 = __fadd_rn(cx, hw2);
        float y2 = __fadd_rn(cy, hh2);
        g_x1[b][i] = x1; g_y1[b][i] = y1; g_x2[b][i] = x2; g_y2[b][i] = y2;
        g_ar[b][i] = __fmul_rn(__fadd_rn(__fsub_rn(x2, x1), 1.0f),
                               __fadd_rn(__fsub_rn(y2, y1), 1.0f));
        g_cl[b][i] = (short)g_cls[b][n];
        if (conf >= 0.5f)
            atomicOr(&s_vab32[i >> 5], 1u << (i & 31));
    }
    __syncthreads();
    if (t < 64) ((unsigned*)g_vab[b])[t] = s_vab32[t];
}

// ---------------------------------------------------------------------------
// Kernel 3: suppression mask (unchanged — measured 19.8us).
// ---------------------------------------------------------------------------
__global__ void nms_mask(void) {
    int jb = blockIdx.x, ib = blockIdx.y, b = blockIdx.z;
    if (jb < ib) return;

    __shared__ float jx1[64], jy1[64], jx2[64], jy2[64], jar[64];
    __shared__ u64 s_cm[NC];

    int t = threadIdx.x;
    int j0 = jb * 64;
    if (t < NC) s_cm[t] = 0ull;
    __syncthreads();
    jx1[t] = g_x1[b][j0 + t];
    jy1[t] = g_y1[b][j0 + t];
    jx2[t] = g_x2[b][j0 + t];
    jy2[t] = g_y2[b][j0 + t];
    jar[t] = g_ar[b][j0 + t];
    atomicOr(&s_cm[g_cl[b][j0 + t]], 1ull << t);
    __syncthreads();

    int i = ib * 64 + t;
    float xi1 = g_x1[b][i], yi1 = g_y1[b][i];
    float xi2 = g_x2[b][i], yi2 = g_y2[b][i];
    float ai  = g_ar[b][i];
    short ci  = g_cl[b][i];

    u64 mm = s_cm[ci];
    if (jb == ib) mm = (t < 63) ? (mm & (~0ull << (t + 1))) : 0ull;

    u64 bits = 0ull;
    while (mm) {
        int jj = __ffsll((long long)mm) - 1;
        mm &= mm - 1;
        float ix1 = fmaxf(xi1, jx1[jj]);
        float iy1 = fmaxf(yi1, jy1[jj]);
        float ix2 = fminf(xi2, jx2[jj]);
        float iy2 = fminf(yi2, jy2[jj]);
        float iw = __fadd_rn(__fsub_rn(ix2, ix1), 1.0f); iw = fmaxf(iw, 0.0f);
        float ih = __fadd_rn(__fsub_rn(iy2, iy1), 1.0f); ih = fmaxf(ih, 0.0f);
        float inter = __fmul_rn(iw, ih);
        float den = __fadd_rn(__fsub_rn(__fadd_rn(ai, jar[jj]), inter), 1e-16f);
        float iou = __fdiv_rn(inter, den);
        if (iou >= 0.4f) bits |= 1ull << jj;
    }
    g_mask[b][i][jb] = bits;
}

// ---------------------------------------------------------------------------
// Kernel 4: block-greedy reduce — 256 threads/batch. Same greedy semantics as
// the round-6 passing kernel; staging and row-apply parallelized over 8 warps.
// ---------------------------------------------------------------------------
__device__ __forceinline__ void cp16(void* saddr, const void* gaddr) {
    unsigned s = (unsigned)__cvta_generic_to_shared(saddr);
    asm volatile("cp.async.cg.shared.global [%0], [%1], 16;" :: "r"(s), "l"(gaddr));
}

__global__ void nms_reduce(float* __restrict__ keep_out) {
    __shared__ __align__(16) u64 sbuf[2][64][NWORDS];   // 32 KB
    __shared__ unsigned s_rem32[64];
    __shared__ u64 s_vab[NWORDS];
    __shared__ u64 s_keep;

    int b = blockIdx.x, t = threadIdx.x;                // 256 threads
    if (t < 64) s_rem32[t] = 0u;
    if (t < NWORDS) s_vab[t] = g_vab[b][t];

    // stage(blk, buf): 64 rows x 256B = 16 KB = 1024 x 16B chunks, 4/thread
#define STAGE(blk, buf_)                                                    \
    {                                                                       \
        _Pragma("unroll")                                                   \
        for (int k = 0; k < 4; k++) {                                       \
            int chunk = t + 256 * k;                                        \
            int row = chunk >> 4, off = (chunk & 15) * 2;                   \
            cp16(&sbuf[buf_][row][off], &g_mask[b][(blk) * 64 + row][off]); \
        }                                                                   \
    }

    STAGE(0, 0);
    asm volatile("cp.async.commit_group;");
    STAGE(1, 1);
    asm volatile("cp.async.commit_group;");
    asm volatile("cp.async.wait_group 1;");
    __syncthreads();

    for (int bk = 0; bk < NBLK; bk++) {
        int buf = bk & 1;

        // single thread resolves the 64-candidate word greedily
        if (t == 0) {
            u64 rem = (u64)s_rem32[2 * bk] | ((u64)s_rem32[2 * bk + 1] << 32);
            u64 cand = s_vab[bk] & ~rem;
            u64 keep64 = 0ull;
            while (cand) {
                int u = __ffsll((long long)cand) - 1;
                keep64 |= 1ull << u;
                cand &= ~(1ull << u);
                cand &= ~sbuf[buf][u][bk];    // diagonal: bits only for j > u
            }
            s_keep = keep64;
        }
        __syncthreads();
        u64 keep64 = s_keep;

        if (t < 64)
            keep_out[b * TOPK + bk * 64 + t] =
                ((keep64 >> t) & 1ull) ? 1.0f : 0.0f;

        // parallel apply: thread (w, g) ORs kept rows u (u%8==g) into word w
        {
            int w = t & 31, g = t >> 5;
            if (w > bk) {
                u64 kk = keep64 & (0x0101010101010101ull << g);
                u64 part = 0ull;
                while (kk) {
                    int u = __ffsll((long long)kk) - 1;
                    kk &= kk - 1;
                    part |= sbuf[buf][u][w];
                }
                if (part) {
                    unsigned lo = (unsigned)part, hi = (unsigned)(part >> 32);
                    if (lo) atomicOr(&s_rem32[2 * w],     lo);
                    if (hi) atomicOr(&s_rem32[2 * w + 1], hi);
                }
            }
        }
        __syncthreads();          // all sbuf[buf] reads done before restage

        if (bk + 2 < NBLK) STAGE(bk + 2, buf);
        asm volatile("cp.async.commit_group;");
        asm volatile("cp.async.wait_group 1;");
        __syncthreads();
    }
#undef STAGE
}

// ---------------------------------------------------------------------------
// Launch: out = [output(B*NBOX*NATTR) | top_idx(B*TOPK) | keep(B*TOPK)] float32
// ---------------------------------------------------------------------------
extern "C" void kernel_launch(void* const* d_in, const int* in_sizes, int n_in,
                              void* d_out, int out_size) {
    (void)in_sizes; (void)n_in; (void)out_size;
    const float* in      = (const float*)d_in[0];
    const float* anchors = (const float*)d_in[1];
    float* out      = (float*)d_out;
    float* top_out  = out + (size_t)BATCH * NBOX * NATTR;
    float* keep_out = top_out + (size_t)BATCH * TOPK;

    int total = BATCH * NBOX;                 // 129792 = 256 * 507, no tail
    decode_kernel<<<total / 256, 256>>>(in, anchors, out);

    local_sort<<<dim3(8, BATCH), 1024>>>();
    merge_pass<1024, 1><<<dim3(4, BATCH), 1024>>>();   // A -> B (full merges)
    merge_pass<2048, 0><<<dim3(2, BATCH), 1024>>>();   // B -> A (truncating)
    merge_final<<<BATCH, 1024>>>(out, top_out);        // A -> outputs + prep

    nms_mask<<<dim3(TOPK / 64, TOPK / 64, BATCH), 64>>>();
    nms_reduce<<<BATCH, 256>>>(keep_out);
}